// round 2
// baseline (speedup 1.0000x reference)
#include <cuda_runtime.h>
#include <math.h>
#include <stdint.h>

// ---------------- problem constants ----------------
#define B_ROWS   16384
#define IN_DIM   2048
#define N_NODES  1023
#define NODE_PAD 1024
#define N_LEAVES 1024
#define OUT_DIM  512
#define DEPTH    10

// ---------------- device scratch (no allocations allowed) ----------------
__device__ float g_P[(size_t)B_ROWS * NODE_PAD];        // sigmoid node probs [B, 1024-padded]
__device__ float g_probs[(size_t)B_ROWS * N_LEAVES];    // leaf probabilities  [B, 1024]
__device__ float g_regpart[128 * NODE_PAD];             // per-block partial log sums

// ==========================================================================
// Tiled fp32 GEMM:  C[M,N] = A[M,K] * B[K,N]   (A,B,C row-major)
// BM=BN=128, BK=16, 256 threads, 8x8 micro-tile/thread, 2-stage double buffer.
// EPI==0 : GEMM1 epilogue -> p = sigmoid(acc + bias[n]); store p
// EPI==1 : plain store
// ==========================================================================
template <int EPI>
__global__ __launch_bounds__(256)
void gemm128_kernel(const float* __restrict__ A,
                    const float* __restrict__ Bm,
                    const float* __restrict__ bias,
                    float* __restrict__ C,
                    int M, int N, int K,
                    int lda, int ldb, int ldc)
{
    __shared__ float As[2][16][128];   // [buf][k][m]  (A stored transposed)
    __shared__ float Bs[2][16][128];   // [buf][k][n]

    const int tid = threadIdx.x;
    const int tx  = tid & 15;          // 0..15 -> N direction (8 cols each)
    const int ty  = tid >> 4;          // 0..15 -> M direction (8 rows each)

    const int row0 = blockIdx.y * 128;
    const int col0 = blockIdx.x * 128;

    // ---- global load mapping ----
    // A tile: 128 rows x 16 cols -> 2 float4 per thread.
    const int a_r = tid >> 1;              // 0..127
    const int a_c = (tid & 1) * 8;         // 0 or 8 (then +0 / +4)
    // B tile: 16 rows x 128 cols -> 8 scalars per thread (rows b_k, b_k+8).
    const int b_k = tid >> 5;              // 0..7
    const int b_n = (tid * 4) & 127;       // 0,4,...,124

    const int numTiles = K >> 4;

    // ---- preload tile 0 ----
    {
        const float4 a0 = *(const float4*)&A[(size_t)(row0 + a_r) * lda + a_c];
        const float4 a1 = *(const float4*)&A[(size_t)(row0 + a_r) * lda + a_c + 4];
        As[0][a_c + 0][a_r] = a0.x;  As[0][a_c + 1][a_r] = a0.y;
        As[0][a_c + 2][a_r] = a0.z;  As[0][a_c + 3][a_r] = a0.w;
        As[0][a_c + 4][a_r] = a1.x;  As[0][a_c + 5][a_r] = a1.y;
        As[0][a_c + 6][a_r] = a1.z;  As[0][a_c + 7][a_r] = a1.w;
        #pragma unroll
        for (int r = 0; r < 2; ++r) {
            const int kk = b_k + r * 8;
            #pragma unroll
            for (int j = 0; j < 4; ++j) {
                const int gn = col0 + b_n + j;
                Bs[0][kk][b_n + j] = (gn < N) ? Bm[(size_t)kk * ldb + gn] : 0.f;
            }
        }
    }
    __syncthreads();

    float acc[8][8];
    #pragma unroll
    for (int i = 0; i < 8; ++i)
        #pragma unroll
        for (int j = 0; j < 8; ++j) acc[i][j] = 0.f;

    float4 aF0, aF1;
    float  bF[8];

    for (int t = 0; t < numTiles; ++t) {
        const int cur = t & 1;
        const int nxt = cur ^ 1;

        // prefetch next tile into registers
        if (t + 1 < numTiles) {
            const int k0 = (t + 1) * 16;
            aF0 = *(const float4*)&A[(size_t)(row0 + a_r) * lda + k0 + a_c];
            aF1 = *(const float4*)&A[(size_t)(row0 + a_r) * lda + k0 + a_c + 4];
            #pragma unroll
            for (int r = 0; r < 2; ++r) {
                const int kk = b_k + r * 8;
                #pragma unroll
                for (int j = 0; j < 4; ++j) {
                    const int gn = col0 + b_n + j;
                    bF[r * 4 + j] = (gn < N) ? Bm[(size_t)(k0 + kk) * ldb + gn] : 0.f;
                }
            }
        }

        // compute on current tile
        #pragma unroll
        for (int kk = 0; kk < 16; ++kk) {
            float ra[8], rb[8];
            const float4 a0 = *(const float4*)&As[cur][kk][ty * 8];
            const float4 a1 = *(const float4*)&As[cur][kk][ty * 8 + 4];
            const float4 b0 = *(const float4*)&Bs[cur][kk][tx * 8];
            const float4 b1 = *(const float4*)&Bs[cur][kk][tx * 8 + 4];
            ra[0]=a0.x; ra[1]=a0.y; ra[2]=a0.z; ra[3]=a0.w;
            ra[4]=a1.x; ra[5]=a1.y; ra[6]=a1.z; ra[7]=a1.w;
            rb[0]=b0.x; rb[1]=b0.y; rb[2]=b0.z; rb[3]=b0.w;
            rb[4]=b1.x; rb[5]=b1.y; rb[6]=b1.z; rb[7]=b1.w;
            #pragma unroll
            for (int i = 0; i < 8; ++i)
                #pragma unroll
                for (int j = 0; j < 8; ++j)
                    acc[i][j] = fmaf(ra[i], rb[j], acc[i][j]);
        }

        // commit prefetched tile to the other buffer
        if (t + 1 < numTiles) {
            As[nxt][a_c + 0][a_r] = aF0.x;  As[nxt][a_c + 1][a_r] = aF0.y;
            As[nxt][a_c + 2][a_r] = aF0.z;  As[nxt][a_c + 3][a_r] = aF0.w;
            As[nxt][a_c + 4][a_r] = aF1.x;  As[nxt][a_c + 5][a_r] = aF1.y;
            As[nxt][a_c + 6][a_r] = aF1.z;  As[nxt][a_c + 7][a_r] = aF1.w;
            #pragma unroll
            for (int r = 0; r < 2; ++r) {
                const int kk = b_k + r * 8;
                #pragma unroll
                for (int j = 0; j < 4; ++j)
                    Bs[nxt][kk][b_n + j] = bF[r * 4 + j];
            }
        }
        __syncthreads();
    }

    // ---- epilogue ----
    #pragma unroll
    for (int i = 0; i < 8; ++i) {
        const int gm = row0 + ty * 8 + i;
        #pragma unroll
        for (int j = 0; j < 8; ++j) {
            const int gn = col0 + tx * 8 + j;
            if (gn < N) {
                if (EPI == 0) {
                    const float z = acc[i][j] + bias[gn];
                    const float p = 1.f / (1.f + __expf(-z));
                    C[(size_t)gm * ldc + gn] = p;
                } else {
                    C[(size_t)gm * ldc + gn] = acc[i][j];
                }
            }
        }
    }
}

// ==========================================================================
// Tree expansion: leaf probs from node probs (one block per batch row)
// ==========================================================================
__global__ __launch_bounds__(256)
void tree_kernel(const float* __restrict__ P, float* __restrict__ probs)
{
    __shared__ float sP[NODE_PAD];
    const int row = blockIdx.x;
    const float* Prow = P + (size_t)row * NODE_PAD;
    for (int i = threadIdx.x; i < N_NODES; i += 256) sP[i] = Prow[i];
    __syncthreads();

    for (int l = threadIdx.x; l < N_LEAVES; l += 256) {
        float prod = 1.f;
        #pragma unroll
        for (int d = 0; d < DEPTH; ++d) {
            const int idx  = l >> (DEPTH - d);
            const int node = (1 << d) - 1 + idx;
            const float p  = sP[node];
            const int bit  = (l >> (DEPTH - 1 - d)) & 1;
            prod *= bit ? (1.f - p) : p;
        }
        probs[(size_t)row * N_LEAVES + l] = prod;
    }
}

// ==========================================================================
// Regularizer stage 1: 128 blocks, each sums log(max(p(1-p),1e-5)) over
// 128 rows per node column. Deterministic (no atomics).
// ==========================================================================
__global__ __launch_bounds__(256)
void reg_partial_kernel(const float* __restrict__ P, float* __restrict__ part)
{
    const int b  = blockIdx.x;        // 0..127
    const int c0 = threadIdx.x;       // column base
    float acc[4] = {0.f, 0.f, 0.f, 0.f};
    for (int r = 0; r < 128; ++r) {
        const float* Prow = P + (size_t)(b * 128 + r) * NODE_PAD;
        #pragma unroll
        for (int j = 0; j < 4; ++j) {
            const int c = c0 + j * 256;
            if (c < N_NODES) {
                const float p = Prow[c];
                acc[j] += __logf(fmaxf(p * (1.f - p), 1e-5f));
            }
        }
    }
    #pragma unroll
    for (int j = 0; j < 4; ++j) {
        const int c = c0 + j * 256;
        if (c < NODE_PAD) part[b * NODE_PAD + c] = (c < N_NODES) ? acc[j] : 0.f;
    }
}

// stage 2 — reduce 128 partials per node, weight by -0.5 * 2^-d / B, sum all.
__global__ __launch_bounds__(1024)
void reg_final_kernel(const float* __restrict__ part, float* __restrict__ out_reg)
{
    __shared__ float red[1024];
    const int c = threadIdx.x;
    float s = 0.f;
    if (c < N_NODES) {
        for (int i = 0; i < 128; ++i) s += part[i * NODE_PAD + c];
        const int d = 31 - __clz(c + 1);
        s = -0.5f * exp2f((float)(-d)) * (s / (float)B_ROWS);
    }
    red[c] = s;
    __syncthreads();
    #pragma unroll
    for (int st = 512; st > 0; st >>= 1) {
        if (c < st) red[c] += red[c + st];
        __syncthreads();
    }
    if (c == 0) *out_reg = red[0];
}

// ==========================================================================
extern "C" void kernel_launch(void* const* d_in, const int* in_sizes, int n_in,
                              void* d_out, int out_size)
{
    const float* x     = (const float*)d_in[0];   // [16384, 2048]
    const float* W     = (const float*)d_in[1];   // [2048, 1023]
    const float* bias  = (const float*)d_in[2];   // [1023]
    const float* value = (const float*)d_in[3];   // [1024, 512]
    float* out = (float*)d_out;

    float *P, *probs, *part;
    cudaGetSymbolAddress((void**)&P,     g_P);
    cudaGetSymbolAddress((void**)&probs, g_probs);
    cudaGetSymbolAddress((void**)&part,  g_regpart);

    // GEMM1: P = sigmoid(x @ W + b)    [16384 x 1023], K=2048
    {
        dim3 grid((N_NODES + 127) / 128, B_ROWS / 128);   // (8, 128)
        gemm128_kernel<0><<<grid, 256>>>(x, W, bias, P,
                                         B_ROWS, N_NODES, IN_DIM,
                                         IN_DIM, N_NODES, NODE_PAD);
    }

    // Tree expansion: probs [16384 x 1024]
    tree_kernel<<<B_ROWS, 256>>>(P, probs);

    // Regularizer partials (independent of tree/GEMM2)
    reg_partial_kernel<<<128, 256>>>(P, part);

    // GEMM2: out = probs @ value      [16384 x 512], K=1024
    {
        dim3 grid(OUT_DIM / 128, B_ROWS / 128);            // (4, 128)
        gemm128_kernel<1><<<grid, 256>>>(probs, value, nullptr, out,
                                         B_ROWS, OUT_DIM, N_LEAVES,
                                         N_LEAVES, OUT_DIM, OUT_DIM);
    }

    // reg scalar appended after the flattened out tensor
    if (out_size > B_ROWS * OUT_DIM) {
        reg_final_kernel<<<1, 1024>>>(part, out + (out_size - 1));
    }
}

// round 5
// speedup vs baseline: 1.5529x; 1.5529x over previous
#include <cuda_runtime.h>
#include <cuda_bf16.h>
#include <math.h>
#include <stdint.h>

// ---------------- problem constants ----------------
#define B_ROWS   16384
#define IN_DIM   2048
#define N_NODES  1023
#define NODE_PAD 1024
#define N_LEAVES 1024
#define OUT_DIM  512
#define DEPTH    10

// ---------------- device scratch (no allocations allowed) ----------------
__device__ float         g_P [(size_t)B_ROWS * NODE_PAD];     // fp32 node probs
__device__ __nv_bfloat16 g_xh[(size_t)B_ROWS * IN_DIM];
__device__ __nv_bfloat16 g_xl[(size_t)B_ROWS * IN_DIM];
__device__ __nv_bfloat16 g_wh[(size_t)NODE_PAD * IN_DIM];     // W^T split, [n][k]
__device__ __nv_bfloat16 g_wl[(size_t)NODE_PAD * IN_DIM];
__device__ __nv_bfloat16 g_vh[(size_t)OUT_DIM * N_LEAVES];    // value^T split, [n][k]
__device__ __nv_bfloat16 g_vl[(size_t)OUT_DIM * N_LEAVES];
__device__ __nv_bfloat16 g_ph[(size_t)B_ROWS * N_LEAVES];     // leaf probs split
__device__ __nv_bfloat16 g_pl[(size_t)B_ROWS * N_LEAVES];
__device__ float         g_regpart[128 * NODE_PAD];

// ==========================================================================
// mma.sync bf16 helpers (sm_80-era PTX: valid on plain sm_103 target)
// ==========================================================================
__device__ __forceinline__ uint32_t smem_u32(const void* p) {
    uint32_t a;
    asm("{ .reg .u64 t; cvta.to.shared.u64 t, %1; cvt.u32.u64 %0, t; }" : "=r"(a) : "l"(p));
    return a;
}
#define LDSM_X4(r, a) \
    asm volatile("ldmatrix.sync.aligned.m8n8.x4.shared.b16 {%0,%1,%2,%3}, [%4];" \
        : "=r"((r)[0]), "=r"((r)[1]), "=r"((r)[2]), "=r"((r)[3]) : "r"(a))

__device__ __forceinline__ void mma_bf16(float c[4], const uint32_t a[4],
                                         uint32_t b0, uint32_t b1) {
    asm volatile(
        "mma.sync.aligned.m16n8k16.row.col.f32.bf16.bf16.f32 "
        "{%0,%1,%2,%3}, {%4,%5,%6,%7}, {%8,%9}, {%0,%1,%2,%3};"
        : "+f"(c[0]), "+f"(c[1]), "+f"(c[2]), "+f"(c[3])
        : "r"(a[0]), "r"(a[1]), "r"(a[2]), "r"(a[3]), "r"(b0), "r"(b1));
}
#define CP_ASYNC16(s, g) \
    asm volatile("cp.async.cg.shared.global [%0], [%1], 16;" :: "r"(s), "l"(g))
#define CP_COMMIT()  asm volatile("cp.async.commit_group;")
#define CP_WAIT1()   asm volatile("cp.async.wait_group 1;")

// ==========================================================================
// bf16-split tensor-core GEMM: C[M,N] = (Ah+Al)@(Bh+Bl)^T  (lo*lo dropped)
// A: [M][K] row-major bf16 (hi/lo).  B: [n][K] k-major bf16 (hi/lo).
// CTA tile 128x128, BK=32, 3-stage cp.async pipeline, 8 warps (2x4),
// warp tile 64x32, m16n8k16, 3 MMAs per fragment pair.
// EPI==0: sigmoid(acc + bias[n]) -> fp32 C ; EPI==1: plain fp32 store
// ==========================================================================
#define ROWH   40            // smem row length in halves (32 data + 8 pad)
#define ROWB   80            // smem row stride bytes
#define MATB   (128 * ROWB)  // one matrix tile (128 rows) = 10240 B
#define STAGEB (4 * MATB)    // Ah, Al, Bh, Bl per stage = 40960 B
#define NSTAGE 3
#define SMEM_DYN (NSTAGE * STAGEB)   // 122880 B

template <int EPI>
__global__ __launch_bounds__(256)
void mma_gemm_kernel(const __nv_bfloat16* __restrict__ Ah,
                     const __nv_bfloat16* __restrict__ Al,
                     const __nv_bfloat16* __restrict__ Bh,
                     const __nv_bfloat16* __restrict__ Bl,
                     const float* __restrict__ bias,
                     float* __restrict__ Cout,
                     int K, int ldc, int Nvalid)
{
    extern __shared__ char smem[];
    const uint32_t sbase = smem_u32(smem);
    const int tid  = threadIdx.x;
    const int wid  = tid >> 5;
    const int lane = tid & 31;
    const int wm   = wid & 1;          // warp row  (2)  -> M 64
    const int wn   = wid >> 1;         // warp col  (4)  -> N 32

    const int row0 = blockIdx.y * 128;
    const int col0 = blockIdx.x * 128;

    const int T = K >> 5;              // k-tiles of 32

    // ---- cp.async mapping: 512 x 16B chunks per matrix, 2 per thread ----
    const int ch_r0  = tid >> 2;             // row of chunk 0   (0..63)
    const int ch_c0  = (tid & 3) << 3;       // half-offset 0/8/16/24
    // chunk 1 = +256 -> row +64
    const __nv_bfloat16* gA[2] = { Ah, Al };
    const __nv_bfloat16* gB[2] = { Bh, Bl };

    // ---- ldmatrix per-lane offsets ----
    const int laA = ((lane & 15) * ROWH + ((lane >> 4) << 3)) * 2;  // A tiles
    const int laB = (((lane & 7) + ((lane >> 4) << 3)) * ROWH + (((lane >> 3) & 1) << 3)) * 2;

    float c[4][4][4];
    #pragma unroll
    for (int i = 0; i < 4; ++i)
        #pragma unroll
        for (int j = 0; j < 4; ++j)
            #pragma unroll
            for (int r = 0; r < 4; ++r) c[i][j][r] = 0.f;

    // ---- stage loader ----
    auto load_stage = [&](int t, int s) {
        const uint32_t sb = sbase + s * STAGEB;
        const int kh = t * 32;                     // k offset in halves
        #pragma unroll
        for (int m = 0; m < 2; ++m) {              // Ah, Al
            const __nv_bfloat16* src = gA[m];
            #pragma unroll
            for (int j = 0; j < 2; ++j) {
                const int r = ch_r0 + j * 64;
                CP_ASYNC16(sb + m * MATB + r * ROWB + ch_c0 * 2,
                           src + (size_t)(row0 + r) * K + kh + ch_c0);
            }
        }
        #pragma unroll
        for (int m = 0; m < 2; ++m) {              // Bh, Bl
            const __nv_bfloat16* src = gB[m];
            #pragma unroll
            for (int j = 0; j < 2; ++j) {
                const int r = ch_r0 + j * 64;
                CP_ASYNC16(sb + (2 + m) * MATB + r * ROWB + ch_c0 * 2,
                           src + (size_t)(col0 + r) * K + kh + ch_c0);
            }
        }
    };

    // ---- prologue: stages 0,1 ----
    load_stage(0, 0); CP_COMMIT();
    load_stage(1, 1); CP_COMMIT();

    int s_cur = 0;
    for (int t = 0; t < T; ++t) {
        CP_WAIT1();
        __syncthreads();

        if (t + 2 < T) load_stage(t + 2, (s_cur + 2) % NSTAGE);
        CP_COMMIT();

        const uint32_t sb = sbase + s_cur * STAGEB;
        const uint32_t aHu = sb,            aLu = sb + MATB;
        const uint32_t bHu = sb + 2 * MATB, bLu = sb + 3 * MATB;

        #pragma unroll
        for (int ks = 0; ks < 2; ++ks) {
            const int ko = ks * 32;   // bytes: 16 halves
            uint32_t ah[4][4], al[4][4], bh[2][4], bl[2][4];
            #pragma unroll
            for (int mi = 0; mi < 4; ++mi) {
                const uint32_t off = (wm * 64 + mi * 16) * ROWB + ko + laA;
                LDSM_X4(ah[mi], aHu + off);
                LDSM_X4(al[mi], aLu + off);
            }
            #pragma unroll
            for (int pr = 0; pr < 2; ++pr) {
                const uint32_t off = (wn * 32 + pr * 16) * ROWB + ko + laB;
                LDSM_X4(bh[pr], bHu + off);
                LDSM_X4(bl[pr], bLu + off);
            }
            #pragma unroll
            for (int mi = 0; mi < 4; ++mi)
                #pragma unroll
                for (int ni = 0; ni < 4; ++ni) {
                    const int pr = ni >> 1, ix = (ni & 1) << 1;
                    mma_bf16(c[mi][ni], ah[mi], bh[pr][ix], bh[pr][ix + 1]);
                    mma_bf16(c[mi][ni], al[mi], bh[pr][ix], bh[pr][ix + 1]);
                    mma_bf16(c[mi][ni], ah[mi], bl[pr][ix], bl[pr][ix + 1]);
                }
        }
        s_cur = (s_cur + 1) % NSTAGE;
    }

    // ---- epilogue ----
    const int er = lane >> 2;            // 0..7
    const int ec = (lane & 3) << 1;      // 0,2,4,6
    #pragma unroll
    for (int mi = 0; mi < 4; ++mi) {
        #pragma unroll
        for (int ni = 0; ni < 4; ++ni) {
            const int gr = row0 + wm * 64 + mi * 16 + er;
            const int gc = col0 + wn * 32 + ni * 8 + ec;
            #pragma unroll
            for (int h = 0; h < 2; ++h) {          // row gr, gr+8
                float v0 = c[mi][ni][h * 2 + 0];
                float v1 = c[mi][ni][h * 2 + 1];
                if (EPI == 0) {
                    const float b0 = (gc + 0 < Nvalid) ? bias[gc + 0] : 0.f;
                    const float b1 = (gc + 1 < Nvalid) ? bias[gc + 1] : 0.f;
                    v0 = 1.f / (1.f + __expf(-(v0 + b0)));
                    v1 = 1.f / (1.f + __expf(-(v1 + b1)));
                }
                float2 st; st.x = v0; st.y = v1;
                *(float2*)&Cout[(size_t)(gr + h * 8) * ldc + gc] = st;
            }
        }
    }
}

// ==========================================================================
// x -> (hi, lo) bf16 split, vectorized
// ==========================================================================
__global__ __launch_bounds__(256)
void xsplit_kernel(const float* __restrict__ x,
                   __nv_bfloat16* __restrict__ hi, __nv_bfloat16* __restrict__ lo)
{
    const size_t i4 = (size_t)blockIdx.x * 256 + threadIdx.x;   // float4 index
    const float4 v = ((const float4*)x)[i4];
    __nv_bfloat16 h0 = __float2bfloat16(v.x), h1 = __float2bfloat16(v.y);
    __nv_bfloat16 h2 = __float2bfloat16(v.z), h3 = __float2bfloat16(v.w);
    __nv_bfloat16 l0 = __float2bfloat16(v.x - __bfloat162float(h0));
    __nv_bfloat16 l1 = __float2bfloat16(v.y - __bfloat162float(h1));
    __nv_bfloat16 l2 = __float2bfloat16(v.z - __bfloat162float(h2));
    __nv_bfloat16 l3 = __float2bfloat16(v.w - __bfloat162float(h3));
    ((__nv_bfloat162*)hi)[i4 * 2 + 0] = __halves2bfloat162(h0, h1);
    ((__nv_bfloat162*)hi)[i4 * 2 + 1] = __halves2bfloat162(h2, h3);
    ((__nv_bfloat162*)lo)[i4 * 2 + 0] = __halves2bfloat162(l0, l1);
    ((__nv_bfloat162*)lo)[i4 * 2 + 1] = __halves2bfloat162(l2, l3);
}

// ==========================================================================
// transpose + split:  src[R][Cv] (row-major) -> hi/lo[Cpad][R] (k-major)
// ==========================================================================
__global__ __launch_bounds__(256)
void tsplit_kernel(const float* __restrict__ src,
                   __nv_bfloat16* __restrict__ hi, __nv_bfloat16* __restrict__ lo,
                   int R, int Cv)
{
    __shared__ float t[32][33];
    const int c0 = blockIdx.x * 32, r0 = blockIdx.y * 32;
    const int tx = threadIdx.x & 31, ty = threadIdx.x >> 5;
    #pragma unroll
    for (int i = 0; i < 4; ++i) {
        const int r = r0 + ty + i * 8, c = c0 + tx;
        t[ty + i * 8][tx] = (c < Cv) ? src[(size_t)r * Cv + c] : 0.f;
    }
    __syncthreads();
    #pragma unroll
    for (int i = 0; i < 4; ++i) {
        const int c = c0 + ty + i * 8, r = r0 + tx;
        const float f = t[tx][ty + i * 8];
        const __nv_bfloat16 h = __float2bfloat16(f);
        const __nv_bfloat16 l = __float2bfloat16(f - __bfloat162float(h));
        hi[(size_t)c * R + r] = h;
        lo[(size_t)c * R + r] = l;
    }
}

// ==========================================================================
// Tree expansion: leaf probs (fp32) -> bf16 hi/lo split
// ==========================================================================
__global__ __launch_bounds__(256)
void tree_kernel(const float* __restrict__ P,
                 __nv_bfloat16* __restrict__ ph, __nv_bfloat16* __restrict__ pl)
{
    __shared__ float sP[NODE_PAD];
    const int row = blockIdx.x;
    const float* Prow = P + (size_t)row * NODE_PAD;
    for (int i = threadIdx.x; i < N_NODES; i += 256) sP[i] = Prow[i];
    __syncthreads();

    for (int lf = threadIdx.x; lf < N_LEAVES; lf += 256) {
        float prod = 1.f;
        #pragma unroll
        for (int d = 0; d < DEPTH; ++d) {
            const int idx  = lf >> (DEPTH - d);
            const int node = (1 << d) - 1 + idx;
            const float p  = sP[node];
            const int bit  = (lf >> (DEPTH - 1 - d)) & 1;
            prod *= bit ? (1.f - p) : p;
        }
        const __nv_bfloat16 h = __float2bfloat16(prod);
        const __nv_bfloat16 l = __float2bfloat16(prod - __bfloat162float(h));
        ph[(size_t)row * N_LEAVES + lf] = h;
        pl[(size_t)row * N_LEAVES + lf] = l;
    }
}

// ==========================================================================
// Regularizer (deterministic two-stage)
// ==========================================================================
__global__ __launch_bounds__(256)
void reg_partial_kernel(const float* __restrict__ P, float* __restrict__ part)
{
    const int b  = blockIdx.x;
    const int c0 = threadIdx.x;
    float acc[4] = {0.f, 0.f, 0.f, 0.f};
    for (int r = 0; r < 128; ++r) {
        const float* Prow = P + (size_t)(b * 128 + r) * NODE_PAD;
        #pragma unroll
        for (int j = 0; j < 4; ++j) {
            const int c = c0 + j * 256;
            if (c < N_NODES) {
                const float p = Prow[c];
                acc[j] += __logf(fmaxf(p * (1.f - p), 1e-5f));
            }
        }
    }
    #pragma unroll
    for (int j = 0; j < 4; ++j) {
        const int c = c0 + j * 256;
        if (c < NODE_PAD) part[b * NODE_PAD + c] = (c < N_NODES) ? acc[j] : 0.f;
    }
}

__global__ __launch_bounds__(1024)
void reg_final_kernel(const float* __restrict__ part, float* __restrict__ out_reg)
{
    __shared__ float red[1024];
    const int c = threadIdx.x;
    float s = 0.f;
    if (c < N_NODES) {
        for (int i = 0; i < 128; ++i) s += part[i * NODE_PAD + c];
        const int d = 31 - __clz(c + 1);
        s = -0.5f * exp2f((float)(-d)) * (s / (float)B_ROWS);
    }
    red[c] = s;
    __syncthreads();
    #pragma unroll
    for (int st = 512; st > 0; st >>= 1) {
        if (c < st) red[c] += red[c + st];
        __syncthreads();
    }
    if (c == 0) *out_reg = red[0];
}

// ==========================================================================
extern "C" void kernel_launch(void* const* d_in, const int* in_sizes, int n_in,
                              void* d_out, int out_size)
{
    const float* x     = (const float*)d_in[0];   // [16384, 2048]
    const float* W     = (const float*)d_in[1];   // [2048, 1023]
    const float* bias  = (const float*)d_in[2];   // [1023]
    const float* value = (const float*)d_in[3];   // [1024, 512]
    float* out = (float*)d_out;

    float *P, *part;
    __nv_bfloat16 *xh, *xl, *wh, *wl, *vh, *vl, *ph, *pl;
    cudaGetSymbolAddress((void**)&P,  g_P);
    cudaGetSymbolAddress((void**)&part, g_regpart);
    cudaGetSymbolAddress((void**)&xh, g_xh);  cudaGetSymbolAddress((void**)&xl, g_xl);
    cudaGetSymbolAddress((void**)&wh, g_wh);  cudaGetSymbolAddress((void**)&wl, g_wl);
    cudaGetSymbolAddress((void**)&vh, g_vh);  cudaGetSymbolAddress((void**)&vl, g_vl);
    cudaGetSymbolAddress((void**)&ph, g_ph);  cudaGetSymbolAddress((void**)&pl, g_pl);

    cudaFuncSetAttribute(mma_gemm_kernel<0>, cudaFuncAttributeMaxDynamicSharedMemorySize, SMEM_DYN);
    cudaFuncSetAttribute(mma_gemm_kernel<1>, cudaFuncAttributeMaxDynamicSharedMemorySize, SMEM_DYN);

    // 1. operand splits
    xsplit_kernel<<<(B_ROWS * IN_DIM) / 1024, 256>>>(x, xh, xl);
    {   // W [2048,1023] -> wh/wl [1024][2048]
        dim3 g(NODE_PAD / 32, IN_DIM / 32);
        tsplit_kernel<<<g, 256>>>(W, wh, wl, IN_DIM, N_NODES);
    }
    {   // value [1024,512] -> vh/vl [512][1024]
        dim3 g(OUT_DIM / 32, N_LEAVES / 32);
        tsplit_kernel<<<g, 256>>>(value, vh, vl, N_LEAVES, OUT_DIM);
    }

    // 2. GEMM1: P = sigmoid(x@W + b)   M=16384, N=1024(pad), K=2048
    {
        dim3 grid(NODE_PAD / 128, B_ROWS / 128);   // (8, 128)
        mma_gemm_kernel<0><<<grid, 256, SMEM_DYN>>>(xh, xl, wh, wl, bias, P,
                                                    IN_DIM, NODE_PAD, N_NODES);
    }

    // 3. tree -> leaf probs (bf16 split)
    tree_kernel<<<B_ROWS, 256>>>(P, ph, pl);

    // 4. regularizer
    reg_partial_kernel<<<128, 256>>>(P, part);
    if (out_size > B_ROWS * OUT_DIM) {
        reg_final_kernel<<<1, 1024>>>(part, out + (out_size - 1));
    }

    // 5. GEMM2: out = probs @ value   M=16384, N=512, K=1024
    {
        dim3 grid(OUT_DIM / 128, B_ROWS / 128);    // (4, 128)
        mma_gemm_kernel<1><<<grid, 256, SMEM_DYN>>>(ph, pl, vh, vl, nullptr, out,
                                                    N_LEAVES, OUT_DIM, OUT_DIM);
    }
}

// round 6
// speedup vs baseline: 2.7176x; 1.7499x over previous
#include <cuda_runtime.h>
#include <cuda_bf16.h>
#include <math.h>
#include <stdint.h>

// ---------------- problem constants ----------------
#define B_ROWS   16384
#define IN_DIM   2048
#define N_NODES  1023
#define NODE_PAD 1024
#define N_LEAVES 1024
#define OUT_DIM  512
#define DEPTH    10

// ---------------- device scratch (no allocations allowed) ----------------
__device__ float         g_P [(size_t)B_ROWS * NODE_PAD];     // fp32 node probs
__device__ __nv_bfloat16 g_xh[(size_t)B_ROWS * IN_DIM];
__device__ __nv_bfloat16 g_xl[(size_t)B_ROWS * IN_DIM];
__device__ __nv_bfloat16 g_wh[(size_t)NODE_PAD * IN_DIM];     // W^T split, [n][k]
__device__ __nv_bfloat16 g_wl[(size_t)NODE_PAD * IN_DIM];
__device__ __nv_bfloat16 g_vh[(size_t)OUT_DIM * N_LEAVES];    // value^T split, [n][k]
__device__ __nv_bfloat16 g_vl[(size_t)OUT_DIM * N_LEAVES];
__device__ __nv_bfloat16 g_ph[(size_t)B_ROWS * N_LEAVES];     // leaf probs split
__device__ __nv_bfloat16 g_pl[(size_t)B_ROWS * N_LEAVES];
__device__ float         g_regpart[128 * NODE_PAD];

// ==========================================================================
// mma.sync bf16 helpers (sm_80-era PTX: valid on plain sm_103 target)
// ==========================================================================
__device__ __forceinline__ uint32_t smem_u32(const void* p) {
    uint32_t a;
    asm("{ .reg .u64 t; cvta.to.shared.u64 t, %1; cvt.u32.u64 %0, t; }" : "=r"(a) : "l"(p));
    return a;
}
#define LDSM_X4(r, a) \
    asm volatile("ldmatrix.sync.aligned.m8n8.x4.shared.b16 {%0,%1,%2,%3}, [%4];" \
        : "=r"((r)[0]), "=r"((r)[1]), "=r"((r)[2]), "=r"((r)[3]) : "r"(a))

__device__ __forceinline__ void mma_bf16(float c[4], const uint32_t a[4],
                                         uint32_t b0, uint32_t b1) {
    asm volatile(
        "mma.sync.aligned.m16n8k16.row.col.f32.bf16.bf16.f32 "
        "{%0,%1,%2,%3}, {%4,%5,%6,%7}, {%8,%9}, {%0,%1,%2,%3};"
        : "+f"(c[0]), "+f"(c[1]), "+f"(c[2]), "+f"(c[3])
        : "r"(a[0]), "r"(a[1]), "r"(a[2]), "r"(a[3]), "r"(b0), "r"(b1));
}
#define CP_ASYNC16(s, g) \
    asm volatile("cp.async.cg.shared.global [%0], [%1], 16;" :: "r"(s), "l"(g))
#define CP_COMMIT()  asm volatile("cp.async.commit_group;")
#define CP_WAIT1()   asm volatile("cp.async.wait_group 1;")

// ==========================================================================
// bf16-split tensor-core GEMM: C[M,N] = (Ah+Al)@(Bh+Bl)^T  (lo*lo dropped)
// A: [M][K] row-major bf16 (hi/lo).  B: [n][K] k-major bf16 (hi/lo).
// CTA tile 128x128, BK=32, 2-stage cp.async double buffer, 8 warps (2x4),
// warp tile 64x32, m16n8k16, 3 MMAs per fragment pair.
// __launch_bounds__(256,2): regs<=128 so 2 CTAs/SM (smem 2x81920 fits).
// EPI==0: sigmoid(acc + bias[n]) -> fp32 C ; EPI==1: plain fp32 store
// ==========================================================================
#define ROWH   40            // smem row length in halves (32 data + 8 pad)
#define ROWB   80            // smem row stride bytes
#define MATB   (128 * ROWB)  // one matrix tile (128 rows) = 10240 B
#define STAGEB (4 * MATB)    // Ah, Al, Bh, Bl per stage = 40960 B
#define NSTAGE 2
#define SMEM_DYN (NSTAGE * STAGEB)   // 81920 B

template <int EPI>
__global__ __launch_bounds__(256, 2)
void mma_gemm_kernel(const __nv_bfloat16* __restrict__ Ah,
                     const __nv_bfloat16* __restrict__ Al,
                     const __nv_bfloat16* __restrict__ Bh,
                     const __nv_bfloat16* __restrict__ Bl,
                     const float* __restrict__ bias,
                     float* __restrict__ Cout,
                     int K, int ldc, int Nvalid)
{
    extern __shared__ char smem[];
    const uint32_t sbase = smem_u32(smem);
    const int tid  = threadIdx.x;
    const int wid  = tid >> 5;
    const int lane = tid & 31;
    const int wm   = wid & 1;          // warp row  (2)  -> M 64
    const int wn   = wid >> 1;         // warp col  (4)  -> N 32

    const int row0 = blockIdx.y * 128;
    const int col0 = blockIdx.x * 128;

    const int T = K >> 5;              // k-tiles of 32

    // ---- cp.async mapping: 512 x 16B chunks per matrix, 2 per thread ----
    const int ch_r0  = tid >> 2;             // row of chunk 0   (0..63)
    const int ch_c0  = (tid & 3) << 3;       // half-offset 0/8/16/24
    const __nv_bfloat16* gA[2] = { Ah, Al };
    const __nv_bfloat16* gB[2] = { Bh, Bl };

    // ---- ldmatrix per-lane offsets ----
    const int laA = ((lane & 15) * ROWH + ((lane >> 4) << 3)) * 2;  // A tiles
    const int laB = (((lane & 7) + ((lane >> 4) << 3)) * ROWH + (((lane >> 3) & 1) << 3)) * 2;

    float c[4][4][4];
    #pragma unroll
    for (int i = 0; i < 4; ++i)
        #pragma unroll
        for (int j = 0; j < 4; ++j)
            #pragma unroll
            for (int r = 0; r < 4; ++r) c[i][j][r] = 0.f;

    // ---- stage loader ----
    auto load_stage = [&](int t, int s) {
        const uint32_t sb = sbase + s * STAGEB;
        const int kh = t * 32;                     // k offset in halves
        #pragma unroll
        for (int m = 0; m < 2; ++m) {              // Ah, Al
            const __nv_bfloat16* src = gA[m];
            #pragma unroll
            for (int j = 0; j < 2; ++j) {
                const int r = ch_r0 + j * 64;
                CP_ASYNC16(sb + m * MATB + r * ROWB + ch_c0 * 2,
                           src + (size_t)(row0 + r) * K + kh + ch_c0);
            }
        }
        #pragma unroll
        for (int m = 0; m < 2; ++m) {              // Bh, Bl
            const __nv_bfloat16* src = gB[m];
            #pragma unroll
            for (int j = 0; j < 2; ++j) {
                const int r = ch_r0 + j * 64;
                CP_ASYNC16(sb + (2 + m) * MATB + r * ROWB + ch_c0 * 2,
                           src + (size_t)(col0 + r) * K + kh + ch_c0);
            }
        }
    };

    // ---- prologue: stage 0 ----
    load_stage(0, 0); CP_COMMIT();

    for (int t = 0; t < T; ++t) {
        const int cur = t & 1;

        // prefetch next tile into the other buffer (freed by the trailing
        // __syncthreads of iteration t-1)
        if (t + 1 < T) load_stage(t + 1, cur ^ 1);
        CP_COMMIT();
        CP_WAIT1();            // stage t complete (all but latest group)
        __syncthreads();

        const uint32_t sb = sbase + cur * STAGEB;
        const uint32_t aHu = sb,            aLu = sb + MATB;
        const uint32_t bHu = sb + 2 * MATB, bLu = sb + 3 * MATB;

        #pragma unroll
        for (int ks = 0; ks < 2; ++ks) {
            const int ko = ks * 32;   // bytes: 16 halves
            uint32_t ah[4][4], al[4][4], bh[2][4], bl[2][4];
            #pragma unroll
            for (int mi = 0; mi < 4; ++mi) {
                const uint32_t off = (wm * 64 + mi * 16) * ROWB + ko + laA;
                LDSM_X4(ah[mi], aHu + off);
                LDSM_X4(al[mi], aLu + off);
            }
            #pragma unroll
            for (int pr = 0; pr < 2; ++pr) {
                const uint32_t off = (wn * 32 + pr * 16) * ROWB + ko + laB;
                LDSM_X4(bh[pr], bHu + off);
                LDSM_X4(bl[pr], bLu + off);
            }
            #pragma unroll
            for (int mi = 0; mi < 4; ++mi)
                #pragma unroll
                for (int ni = 0; ni < 4; ++ni) {
                    const int pr = ni >> 1, ix = (ni & 1) << 1;
                    mma_bf16(c[mi][ni], ah[mi], bh[pr][ix], bh[pr][ix + 1]);
                    mma_bf16(c[mi][ni], al[mi], bh[pr][ix], bh[pr][ix + 1]);
                    mma_bf16(c[mi][ni], ah[mi], bl[pr][ix], bl[pr][ix + 1]);
                }
        }
        __syncthreads();       // all warps done with buffer `cur` before reuse
    }

    // ---- epilogue ----
    const int er = lane >> 2;            // 0..7
    const int ec = (lane & 3) << 1;      // 0,2,4,6
    #pragma unroll
    for (int mi = 0; mi < 4; ++mi) {
        #pragma unroll
        for (int ni = 0; ni < 4; ++ni) {
            const int gr = row0 + wm * 64 + mi * 16 + er;
            const int gc = col0 + wn * 32 + ni * 8 + ec;
            #pragma unroll
            for (int h = 0; h < 2; ++h) {          // row gr, gr+8
                float v0 = c[mi][ni][h * 2 + 0];
                float v1 = c[mi][ni][h * 2 + 1];
                if (EPI == 0) {
                    const float b0 = (gc + 0 < Nvalid) ? bias[gc + 0] : 0.f;
                    const float b1 = (gc + 1 < Nvalid) ? bias[gc + 1] : 0.f;
                    v0 = 1.f / (1.f + __expf(-(v0 + b0)));
                    v1 = 1.f / (1.f + __expf(-(v1 + b1)));
                }
                float2 st; st.x = v0; st.y = v1;
                *(float2*)&Cout[(size_t)(gr + h * 8) * ldc + gc] = st;
            }
        }
    }
}

// ==========================================================================
// x -> (hi, lo) bf16 split, vectorized
// ==========================================================================
__global__ __launch_bounds__(256)
void xsplit_kernel(const float* __restrict__ x,
                   __nv_bfloat16* __restrict__ hi, __nv_bfloat16* __restrict__ lo)
{
    const size_t i4 = (size_t)blockIdx.x * 256 + threadIdx.x;   // float4 index
    const float4 v = ((const float4*)x)[i4];
    __nv_bfloat16 h0 = __float2bfloat16(v.x), h1 = __float2bfloat16(v.y);
    __nv_bfloat16 h2 = __float2bfloat16(v.z), h3 = __float2bfloat16(v.w);
    __nv_bfloat16 l0 = __float2bfloat16(v.x - __bfloat162float(h0));
    __nv_bfloat16 l1 = __float2bfloat16(v.y - __bfloat162float(h1));
    __nv_bfloat16 l2 = __float2bfloat16(v.z - __bfloat162float(h2));
    __nv_bfloat16 l3 = __float2bfloat16(v.w - __bfloat162float(h3));
    ((__nv_bfloat162*)hi)[i4 * 2 + 0] = __halves2bfloat162(h0, h1);
    ((__nv_bfloat162*)hi)[i4 * 2 + 1] = __halves2bfloat162(h2, h3);
    ((__nv_bfloat162*)lo)[i4 * 2 + 0] = __halves2bfloat162(l0, l1);
    ((__nv_bfloat162*)lo)[i4 * 2 + 1] = __halves2bfloat162(l2, l3);
}

// ==========================================================================
// transpose + split:  src[R][Cv] (row-major) -> hi/lo[Cpad][R] (k-major)
// ==========================================================================
__global__ __launch_bounds__(256)
void tsplit_kernel(const float* __restrict__ src,
                   __nv_bfloat16* __restrict__ hi, __nv_bfloat16* __restrict__ lo,
                   int R, int Cv)
{
    __shared__ float t[32][33];
    const int c0 = blockIdx.x * 32, r0 = blockIdx.y * 32;
    const int tx = threadIdx.x & 31, ty = threadIdx.x >> 5;
    #pragma unroll
    for (int i = 0; i < 4; ++i) {
        const int r = r0 + ty + i * 8, c = c0 + tx;
        t[ty + i * 8][tx] = (c < Cv) ? src[(size_t)r * Cv + c] : 0.f;
    }
    __syncthreads();
    #pragma unroll
    for (int i = 0; i < 4; ++i) {
        const int c = c0 + ty + i * 8, r = r0 + tx;
        const float f = t[tx][ty + i * 8];
        const __nv_bfloat16 h = __float2bfloat16(f);
        const __nv_bfloat16 l = __float2bfloat16(f - __bfloat162float(h));
        hi[(size_t)c * R + r] = h;
        lo[(size_t)c * R + r] = l;
    }
}

// ==========================================================================
// Tree expansion: leaf probs (fp32) -> bf16 hi/lo split
// ==========================================================================
__global__ __launch_bounds__(256)
void tree_kernel(const float* __restrict__ P,
                 __nv_bfloat16* __restrict__ ph, __nv_bfloat16* __restrict__ pl)
{
    __shared__ float sP[NODE_PAD];
    const int row = blockIdx.x;
    const float* Prow = P + (size_t)row * NODE_PAD;
    for (int i = threadIdx.x; i < N_NODES; i += 256) sP[i] = Prow[i];
    __syncthreads();

    for (int lf = threadIdx.x; lf < N_LEAVES; lf += 256) {
        float prod = 1.f;
        #pragma unroll
        for (int d = 0; d < DEPTH; ++d) {
            const int idx  = lf >> (DEPTH - d);
            const int node = (1 << d) - 1 + idx;
            const float p  = sP[node];
            const int bit  = (lf >> (DEPTH - 1 - d)) & 1;
            prod *= bit ? (1.f - p) : p;
        }
        const __nv_bfloat16 h = __float2bfloat16(prod);
        const __nv_bfloat16 l = __float2bfloat16(prod - __bfloat162float(h));
        ph[(size_t)row * N_LEAVES + lf] = h;
        pl[(size_t)row * N_LEAVES + lf] = l;
    }
}

// ==========================================================================
// Regularizer (deterministic two-stage)
// ==========================================================================
__global__ __launch_bounds__(256)
void reg_partial_kernel(const float* __restrict__ P, float* __restrict__ part)
{
    const int b  = blockIdx.x;
    const int c0 = threadIdx.x;
    float acc[4] = {0.f, 0.f, 0.f, 0.f};
    for (int r = 0; r < 128; ++r) {
        const float* Prow = P + (size_t)(b * 128 + r) * NODE_PAD;
        #pragma unroll
        for (int j = 0; j < 4; ++j) {
            const int c = c0 + j * 256;
            if (c < N_NODES) {
                const float p = Prow[c];
                acc[j] += __logf(fmaxf(p * (1.f - p), 1e-5f));
            }
        }
    }
    #pragma unroll
    for (int j = 0; j < 4; ++j) {
        const int c = c0 + j * 256;
        if (c < NODE_PAD) part[b * NODE_PAD + c] = (c < N_NODES) ? acc[j] : 0.f;
    }
}

__global__ __launch_bounds__(1024)
void reg_final_kernel(const float* __restrict__ part, float* __restrict__ out_reg)
{
    __shared__ float red[1024];
    const int c = threadIdx.x;
    float s = 0.f;
    if (c < N_NODES) {
        for (int i = 0; i < 128; ++i) s += part[i * NODE_PAD + c];
        const int d = 31 - __clz(c + 1);
        s = -0.5f * exp2f((float)(-d)) * (s / (float)B_ROWS);
    }
    red[c] = s;
    __syncthreads();
    #pragma unroll
    for (int st = 512; st > 0; st >>= 1) {
        if (c < st) red[c] += red[c + st];
        __syncthreads();
    }
    if (c == 0) *out_reg = red[0];
}

// ==========================================================================
extern "C" void kernel_launch(void* const* d_in, const int* in_sizes, int n_in,
                              void* d_out, int out_size)
{
    const float* x     = (const float*)d_in[0];   // [16384, 2048]
    const float* W     = (const float*)d_in[1];   // [2048, 1023]
    const float* bias  = (const float*)d_in[2];   // [1023]
    const float* value = (const float*)d_in[3];   // [1024, 512]
    float* out = (float*)d_out;

    float *P, *part;
    __nv_bfloat16 *xh, *xl, *wh, *wl, *vh, *vl, *ph, *pl;
    cudaGetSymbolAddress((void**)&P,  g_P);
    cudaGetSymbolAddress((void**)&part, g_regpart);
    cudaGetSymbolAddress((void**)&xh, g_xh);  cudaGetSymbolAddress((void**)&xl, g_xl);
    cudaGetSymbolAddress((void**)&wh, g_wh);  cudaGetSymbolAddress((void**)&wl, g_wl);
    cudaGetSymbolAddress((void**)&vh, g_vh);  cudaGetSymbolAddress((void**)&vl, g_vl);
    cudaGetSymbolAddress((void**)&ph, g_ph);  cudaGetSymbolAddress((void**)&pl, g_pl);

    cudaFuncSetAttribute(mma_gemm_kernel<0>, cudaFuncAttributeMaxDynamicSharedMemorySize, SMEM_DYN);
    cudaFuncSetAttribute(mma_gemm_kernel<1>, cudaFuncAttributeMaxDynamicSharedMemorySize, SMEM_DYN);

    // 1. operand splits
    xsplit_kernel<<<(B_ROWS * IN_DIM) / 1024, 256>>>(x, xh, xl);
    {   // W [2048,1023] -> wh/wl [1024][2048]
        dim3 g(NODE_PAD / 32, IN_DIM / 32);
        tsplit_kernel<<<g, 256>>>(W, wh, wl, IN_DIM, N_NODES);
    }
    {   // value [1024,512] -> vh/vl [512][1024]
        dim3 g(OUT_DIM / 32, N_LEAVES / 32);
        tsplit_kernel<<<g, 256>>>(value, vh, vl, N_LEAVES, OUT_DIM);
    }

    // 2. GEMM1: P = sigmoid(x@W + b)   M=16384, N=1024(pad), K=2048
    {
        dim3 grid(NODE_PAD / 128, B_ROWS / 128);   // (8, 128)
        mma_gemm_kernel<0><<<grid, 256, SMEM_DYN>>>(xh, xl, wh, wl, bias, P,
                                                    IN_DIM, NODE_PAD, N_NODES);
    }

    // 3. tree -> leaf probs (bf16 split)
    tree_kernel<<<B_ROWS, 256>>>(P, ph, pl);

    // 4. regularizer
    reg_partial_kernel<<<128, 256>>>(P, part);
    if (out_size > B_ROWS * OUT_DIM) {
        reg_final_kernel<<<1, 1024>>>(part, out + (out_size - 1));
    }

    // 5. GEMM2: out = probs @ value   M=16384, N=512, K=1024
    {
        dim3 grid(OUT_DIM / 128, B_ROWS / 128);    // (4, 128)
        mma_gemm_kernel<1><<<grid, 256, SMEM_DYN>>>(ph, pl, vh, vl, nullptr, out,
                                                    N_LEAVES, OUT_DIM, OUT_DIM);
    }
}